// round 5
// baseline (speedup 1.0000x reference)
#include <cuda_runtime.h>

// out[n,i] = sum_{m<K} W[i, m*D+i] * h_r[n, m*D+i] + b[i]
// N=8192, D=1024, K=8. HBM streaming: 256MB read + 32MB write.
// At the HBM wall (~6.1 TB/s). This round: kill the work-distribution
// tail — 512 CTAs x exactly 16 contiguous rows each (zero imbalance).

constexpr int D = 1024;
constexpr int K = 8;
constexpr int KD = K * D;           // 8192
constexpr int THREADS = 256;        // thread t owns output cols [4t, 4t+4)
constexpr int GRID = 512;           // 8192 rows / 512 = exactly 16 rows/CTA
constexpr int ROWS_PER_CTA = 16;

// Gathered diagonal of W: g_wd[m*D + i] = W[i, m*D + i]
__device__ float g_wd[KD];

__global__ void gather_wdiag_kernel(const float* __restrict__ W) {
    const int idx = blockIdx.x * blockDim.x + threadIdx.x;
    if (idx < KD) {
        const int m = idx >> 10;
        const int i = idx & (D - 1);
        g_wd[idx] = W[(size_t)i * KD + m * D + i];
    }
}

__global__ __launch_bounds__(THREADS, 4)
void imputation_kernel(const float* __restrict__ h_r,
                       const float* __restrict__ b,
                       float* __restrict__ out,
                       int n_rows) {
    __shared__ float4 wd4[K][THREADS];

    const int t = threadIdx.x;

    // --- PDL prologue: everything NOT depending on g_wd ---
    const float4 breg = reinterpret_cast<const float4*>(b)[t];
    const float4* __restrict__ h4 = reinterpret_cast<const float4*>(h_r);
    float4* __restrict__ o4 = reinterpret_cast<float4*>(out);

    // Wait for gather_wdiag_kernel to complete (PDL dependency).
    cudaGridDependencySynchronize();

    // Coalesced load of the pre-gathered diagonal (8 KB, L2-resident).
    const float4* gw4 = reinterpret_cast<const float4*>(g_wd);
    #pragma unroll
    for (int m = 0; m < K; m++) {
        wd4[m][t] = gw4[m * THREADS + t];
    }
    __syncthreads();

    // Each CTA streams a contiguous 512 KB region: rows [c*16, c*16+16).
    const int row0 = blockIdx.x * ROWS_PER_CTA;
    const int row_end = min(row0 + ROWS_PER_CTA, n_rows);

    for (int n = row0; n < row_end; n++) {
        const float4* __restrict__ hp = h4 + (size_t)n * (KD / 4);

        // 8 independent streaming loads in flight (MLP=8 per thread).
        float4 h[K];
        #pragma unroll
        for (int m = 0; m < K; m++) {
            h[m] = __ldcs(&hp[m * (D / 4) + t]);
        }

        float4 acc = breg;
        #pragma unroll
        for (int m = 0; m < K; m++) {
            const float4 w = wd4[m][t];   // LDS.128, conflict-free
            acc.x = fmaf(h[m].x, w.x, acc.x);
            acc.y = fmaf(h[m].y, w.y, acc.y);
            acc.z = fmaf(h[m].z, w.z, acc.z);
            acc.w = fmaf(h[m].w, w.w, acc.w);
        }

        __stcs(&o4[(size_t)n * (D / 4) + t], acc);
    }
}

extern "C" void kernel_launch(void* const* d_in, const int* in_sizes, int n_in,
                              void* d_out, int out_size) {
    const float* h_r = (const float*)d_in[0];
    const float* W   = (const float*)d_in[1];
    const float* b   = (const float*)d_in[2];
    float* out       = (float*)d_out;

    const int n_rows = in_sizes[0] / KD;   // 8192

    gather_wdiag_kernel<<<(KD + 255) / 256, 256>>>(W);

    // PDL: main kernel boots + runs g_wd-independent prologue while the
    // gather kernel finishes.
    cudaLaunchConfig_t cfg = {};
    cfg.gridDim = dim3(GRID, 1, 1);
    cfg.blockDim = dim3(THREADS, 1, 1);
    cfg.dynamicSmemBytes = 0;
    cfg.stream = 0;
    cudaLaunchAttribute attrs[1];
    attrs[0].id = cudaLaunchAttributeProgrammaticStreamSerialization;
    attrs[0].val.programmaticStreamSerializationAllowed = 1;
    cfg.attrs = attrs;
    cfg.numAttrs = 1;
    cudaLaunchKernelEx(&cfg, imputation_kernel, h_r, b, out, n_rows);
}

// round 6
// speedup vs baseline: 1.0536x; 1.0536x over previous
#include <cuda_runtime.h>

// out[n,i] = sum_{m<K} W[i, m*D+i] * h_r[n, m*D+i] + b[i]
// N=8192, D=1024, K=8. HBM streaming: 256MB read + 32MB write.
// R4 config (608 persistent CTAs + PDL) restored; this round: cached
// (write-back) output stores so dirty lines linger in L2 and write back
// in bursts instead of interleaving with the read stream.

constexpr int D = 1024;
constexpr int K = 8;
constexpr int KD = K * D;           // 8192
constexpr int THREADS = 256;        // thread t owns output cols [4t, 4t+4)
constexpr int CTAS_PER_SM = 4;
constexpr int NUM_SMS = 152;        // GB300
constexpr int GRID = CTAS_PER_SM * NUM_SMS;   // 608 persistent CTAs

// Gathered diagonal of W: g_wd[m*D + i] = W[i, m*D + i]
__device__ float g_wd[KD];

__global__ void gather_wdiag_kernel(const float* __restrict__ W) {
    const int idx = blockIdx.x * blockDim.x + threadIdx.x;
    if (idx < KD) {
        const int m = idx >> 10;
        const int i = idx & (D - 1);
        g_wd[idx] = W[(size_t)i * KD + m * D + i];
    }
}

__global__ __launch_bounds__(THREADS, CTAS_PER_SM)
void imputation_kernel(const float* __restrict__ h_r,
                       const float* __restrict__ b,
                       float* __restrict__ out,
                       int n_rows) {
    __shared__ float4 wd4[K][THREADS];

    const int t = threadIdx.x;

    // --- PDL prologue: everything NOT depending on g_wd ---
    const float4 breg = reinterpret_cast<const float4*>(b)[t];
    const float4* __restrict__ h4 = reinterpret_cast<const float4*>(h_r);
    float4* __restrict__ o4 = reinterpret_cast<float4*>(out);

    // Wait for gather_wdiag_kernel to complete (PDL dependency).
    cudaGridDependencySynchronize();

    // Coalesced load of the pre-gathered diagonal (8 KB, L2-resident).
    const float4* gw4 = reinterpret_cast<const float4*>(g_wd);
    #pragma unroll
    for (int m = 0; m < K; m++) {
        wd4[m][t] = gw4[m * THREADS + t];
    }
    __syncthreads();

    // Persistent grid-stride over rows (608 CTAs, 4/SM everywhere).
    for (int n = blockIdx.x; n < n_rows; n += GRID) {
        const float4* __restrict__ hp = h4 + (size_t)n * (KD / 4);

        // 8 independent streaming (evict-first) loads in flight.
        float4 h[K];
        #pragma unroll
        for (int m = 0; m < K; m++) {
            h[m] = __ldcs(&hp[m * (D / 4) + t]);
        }

        float4 acc = breg;
        #pragma unroll
        for (int m = 0; m < K; m++) {
            const float4 w = wd4[m][t];   // LDS.128, conflict-free
            acc.x = fmaf(h[m].x, w.x, acc.x);
            acc.y = fmaf(h[m].y, w.y, acc.y);
            acc.z = fmaf(h[m].z, w.z, acc.z);
            acc.w = fmaf(h[m].w, w.w, acc.w);
        }

        // Cached write-back store: dirty line parks in L2, flushed in
        // bursts later instead of interleaving with the read stream.
        o4[(size_t)n * (D / 4) + t] = acc;
    }
}

extern "C" void kernel_launch(void* const* d_in, const int* in_sizes, int n_in,
                              void* d_out, int out_size) {
    const float* h_r = (const float*)d_in[0];
    const float* W   = (const float*)d_in[1];
    const float* b   = (const float*)d_in[2];
    float* out       = (float*)d_out;

    const int n_rows = in_sizes[0] / KD;   // 8192

    gather_wdiag_kernel<<<(KD + 255) / 256, 256>>>(W);

    // PDL: main kernel boots + runs g_wd-independent prologue while the
    // gather kernel finishes.
    cudaLaunchConfig_t cfg = {};
    cfg.gridDim = dim3(GRID, 1, 1);
    cfg.blockDim = dim3(THREADS, 1, 1);
    cfg.dynamicSmemBytes = 0;
    cfg.stream = 0;
    cudaLaunchAttribute attrs[1];
    attrs[0].id = cudaLaunchAttributeProgrammaticStreamSerialization;
    attrs[0].val.programmaticStreamSerializationAllowed = 1;
    cfg.attrs = attrs;
    cfg.numAttrs = 1;
    cudaLaunchKernelEx(&cfg, imputation_kernel, h_r, b, out, n_rows);
}